// round 3
// baseline (speedup 1.0000x reference)
#include <cuda_runtime.h>
#include <cstdint>

#define BB 1024
#define LL 512
#define TT 50
#define NT 48
#define START_TAG 48
#define STOP_TAG  49

typedef unsigned long long u64;

__device__ float g_nll[BB];
__device__ int   g_perm[BB];

__device__ __forceinline__ u64 pack2(float x, float y) {
    u64 u; asm("mov.b64 %0, {%1,%2};" : "=l"(u) : "f"(x), "f"(y)); return u;
}
__device__ __forceinline__ void unpack2(u64 u, float &x, float &y) {
    asm("mov.b64 {%0,%1}, %2;" : "=f"(x), "=f"(y) : "l"(u));
}
__device__ __forceinline__ u64 fma2(u64 a, u64 b, u64 c) {
    u64 d; asm("fma.rn.f32x2 %0, %1, %2, %3;" : "=l"(d) : "l"(a), "l"(b), "l"(c)); return d;
}
// warp max of NON-NEGATIVE floats via single integer redux
__device__ __forceinline__ float warp_max_pos(float x) {
    int r; asm("redux.sync.max.s32 %0, %1, 0xffffffff;" : "=r"(r) : "r"(__float_as_int(x)));
    return __int_as_float(r);
}

// ---------- scheduling: counting sort of chains by descending len ----------
__global__ __launch_bounds__(1024) void crf_sort_kernel(const int* __restrict__ lens) {
    __shared__ int hist[512];
    __shared__ int sc[512];
    int tid = threadIdx.x;
    if (tid < 512) hist[tid] = 0;
    __syncthreads();
    int key = 512 - lens[tid];          // len in [1,512] -> key in [0,511], descending len
    atomicAdd(&hist[key], 1);
    __syncthreads();
    int orig = (tid < 512) ? hist[tid] : 0;
    int v = orig;
    // Hillis-Steele inclusive scan over 512 bins
    for (int off = 1; off < 512; off <<= 1) {
        if (tid < 512) sc[tid] = v;
        __syncthreads();
        if (tid < 512 && tid >= off) v += sc[tid - off];
        __syncthreads();
    }
    if (tid < 512) sc[tid] = v - orig;  // exclusive offsets
    __syncthreads();
    int pos = atomicAdd(&sc[key], 1);
    g_perm[pos] = tid;
}

// ---------- forward kernel: 1 warp per CTA, 2 chains per warp ----------
// Lane pair (2m, 2m+1) owns outputs jF=3m+(l&1) fully and shares jS=3m+2
// (k-halves, combined with one shfl). s kept in exp domain with exact
// power-of-2 renorm every 4 steps.
__global__ __launch_bounds__(32) void crf_fwd_kernel(
    const float* __restrict__ logits,   // [B, L, T]
    const float* __restrict__ trans,    // [T, T]
    const int*   __restrict__ labels,   // [B, L]
    const int*   __restrict__ lens)     // [B]
{
    __shared__ __align__(16) u64 sbuf[2][2][24];   // [chain][pingpong][kpair] = float s[48]

    const int  l   = threadIdx.x;
    const int  m   = l >> 1;
    const bool odd = (l & 1);
    const int  jF  = 3 * m + (odd ? 1 : 0);
    const int  jS  = 3 * m + 2;
    const int  shb = odd ? 6 : 0;       // shared half: kk-pairs [shb*2, shb*2+12)

    // Texp register tiles (exp(-1e4) underflows to exactly 0 == semiring zero)
    u64 rF[24], rS[12];
#pragma unroll
    for (int kk = 0; kk < 24; kk++)
        rF[kk] = pack2(__expf(trans[jF * TT + 2 * kk]), __expf(trans[jF * TT + 2 * kk + 1]));
#pragma unroll
    for (int q = 0; q < 12; q++) {
        int kk = shb * 2 + q;
        rS[q] = pack2(__expf(trans[jS * TT + 2 * kk]), __expf(trans[jS * TT + 2 * kk + 1]));
    }
    const float tsF = __expf(trans[STOP_TAG * TT + jF]);
    const float tsS = __expf(trans[STOP_TAG * TT + jS]);
    const u64   ONE = pack2(1.0f, 1.0f);

    const int bA = g_perm[2 * blockIdx.x];
    const int bB = g_perm[2 * blockIdx.x + 1];
    const int lenA = lens[bA];
    const int lenB = lens[bB];          // lenA >= lenB (sorted descending)
    const float* lgA = logits + (size_t)bA * (LL * TT);
    const float* lgB = logits + (size_t)bB * (LL * TT);

    int   EA = 0, EB = 0, EcapA = 0, EcapB = 0;
    float wpA = 0.0f, wpB = 0.0f;
    float pfFA[2], pfSA[2], pfFB[2], pfSB[2];

    // ---- t = 0 closed form: s[j] = exp(trans[j,START] + logit0[j])
#define STEP0(X, CI) do {                                                        \
        float sF = __expf(trans[jF * TT + START_TAG] + lg##X[jF]);               \
        float sS = odd ? __expf(trans[jS * TT + START_TAG] + lg##X[jS]) : 0.0f;  \
        float* sw = (float*)sbuf[CI][1];                                         \
        sw[jF] = sF;                                                             \
        if (odd) sw[jS] = sS;                                                    \
        if (len##X == 1) { wp##X = sF * tsF + (odd ? sS * tsS : 0.0f); Ecap##X = 0; } \
        int i1 = min(1, len##X - 1), i2 = min(2, len##X - 1);                    \
        pfFA[0] = pfFA[0]; /* no-op to quiet unused in macro reuse */            \
        pfF##X[1] = lg##X[i1 * TT + jF];                                         \
        pfS##X[1] = odd ? lg##X[i1 * TT + jS] : 0.0f;                            \
        pfF##X[0] = lg##X[i2 * TT + jF];                                         \
        pfS##X[0] = odd ? lg##X[i2 * TT + jS] : 0.0f;                            \
    } while (0)

    STEP0(A, 0);
    STEP0(B, 1);
    __syncwarp();

#define STEP(X, CI) do { if (t < len##X) {                                       \
        float cF = pfF##X[t & 1];                                                \
        float cS = pfS##X[t & 1];                                                \
        { int pidx = min(t + 2, len##X - 1);                                     \
          const float* rp = lg##X + (size_t)pidx * TT;                           \
          pfF##X[t & 1] = rp[jF];                                                \
          pfS##X[t & 1] = odd ? rp[jS] : 0.0f; }                                 \
        const ulonglong2* sb = (const ulonglong2*)sbuf[CI][t & 1];               \
        u64 a0 = 0ull, a1 = 0ull, as0 = 0ull, as1 = 0ull;                        \
        _Pragma("unroll")                                                        \
        for (int q = 0; q < 12; q++) {                                           \
            ulonglong2 sp = sb[q];                                               \
            a0 = fma2(rF[2 * q],     sp.x, a0);                                  \
            a1 = fma2(rF[2 * q + 1], sp.y, a1);                                  \
        }                                                                        \
        _Pragma("unroll")                                                        \
        for (int q = 0; q < 6; q++) {                                            \
            ulonglong2 sp = sb[shb + q];                                         \
            as0 = fma2(rS[2 * q],     sp.x, as0);                                \
            as1 = fma2(rS[2 * q + 1], sp.y, as1);                                \
        }                                                                        \
        u64 af = fma2(ONE, a1, a0);                                              \
        float f0, f1; unpack2(af, f0, f1);                                       \
        float pF = f0 + f1;                                                      \
        u64 ash = fma2(ONE, as1, as0);                                           \
        float g0, g1; unpack2(ash, g0, g1);                                      \
        float pShHalf = g0 + g1;                                                 \
        float pSh = pShHalf + __shfl_xor_sync(0xffffffffu, pShHalf, 1);          \
        float sF = pF * __expf(cF);                                              \
        float sS = odd ? pSh * __expf(cS) : 0.0f;                                \
        if ((t & 3) == 3) {                                                      \
            float mx = warp_max_pos(fmaxf(sF, sS));                              \
            int e = (__float_as_int(mx) >> 23) - 127;                            \
            float scf = __int_as_float((127 - e) << 23);                         \
            sF *= scf; sS *= scf; E##X += e;                                     \
        }                                                                        \
        float* sw = (float*)sbuf[CI][(t + 1) & 1];                               \
        sw[jF] = sF;                                                             \
        if (odd) sw[jS] = sS;                                                    \
        if (t == len##X - 1) { wp##X = sF * tsF + (odd ? sS * tsS : 0.0f);       \
                               Ecap##X = E##X; }                                 \
    } } while (0)

#pragma unroll 2
    for (int t = 1; t < lenA; t++) {
        STEP(A, 0);
        STEP(B, 1);
        __syncwarp();
    }

    // ---- finalize: partition + gold score per chain
#define FINISH(X) do {                                                           \
        float w = wp##X;                                                         \
        _Pragma("unroll")                                                        \
        for (int o = 16; o; o >>= 1) w += __shfl_xor_sync(0xffffffffu, w, o);    \
        float part = logf(w) + (float)Ecap##X * 0.69314718055994530942f;         \
        const int* labs = labels + (size_t)b##X * LL;                            \
        float gold = 0.0f;                                                       \
        for (int t2 = l; t2 < len##X; t2 += 32) {                                \
            int lab  = labs[t2];                                                 \
            int prev = t2 ? labs[t2 - 1] : START_TAG;                            \
            gold += lg##X[(size_t)t2 * TT + lab] + trans[lab * TT + prev];       \
        }                                                                        \
        _Pragma("unroll")                                                        \
        for (int o = 16; o; o >>= 1) gold += __shfl_xor_sync(0xffffffffu, gold, o); \
        if (l == 0)                                                              \
            g_nll[b##X] = part - (gold + trans[STOP_TAG * TT + labs[len##X - 1]]); \
    } while (0)

    FINISH(A);
    FINISH(B);
}

__global__ __launch_bounds__(1024) void crf_reduce_kernel(float* __restrict__ out) {
    __shared__ float sh[32];
    int tid = threadIdx.x;
    float s = g_nll[tid];
#pragma unroll
    for (int o = 16; o; o >>= 1) s += __shfl_xor_sync(0xffffffffu, s, o);
    if ((tid & 31) == 0) sh[tid >> 5] = s;
    __syncthreads();
    if (tid < 32) {
        float v = sh[tid];
#pragma unroll
        for (int o = 16; o; o >>= 1) v += __shfl_xor_sync(0xffffffffu, v, o);
        if (tid == 0) out[0] = v / (float)BB;
    }
}

extern "C" void kernel_launch(void* const* d_in, const int* in_sizes, int n_in,
                              void* d_out, int out_size) {
    const float* logits = (const float*)d_in[0];
    const float* trans  = (const float*)d_in[1];
    const int*   labels = (const int*)d_in[2];
    const int*   lens   = (const int*)d_in[3];

    crf_sort_kernel<<<1, 1024>>>(lens);
    crf_fwd_kernel<<<BB / 2, 32>>>(logits, trans, labels, lens);
    crf_reduce_kernel<<<1, 1024>>>((float*)d_out);
}

// round 5
// speedup vs baseline: 1.2657x; 1.2657x over previous
#include <cuda_runtime.h>
#include <cstdint>

#define BB 1024
#define LL 512
#define TT 50
#define NT 48
#define START_TAG 48
#define STOP_TAG  49

typedef unsigned long long u64;

__device__ float g_nll[BB];

__device__ __forceinline__ u64 pack2(float x, float y) {
    u64 u; asm("mov.b64 %0, {%1,%2};" : "=l"(u) : "f"(x), "f"(y)); return u;
}
__device__ __forceinline__ void unpack2(u64 u, float &x, float &y) {
    asm("mov.b64 {%0,%1}, %2;" : "=f"(x), "=f"(y) : "l"(u));
}
// Blackwell packed f32x2 FMA
__device__ __forceinline__ u64 fma2(u64 a, u64 b, u64 c) {
    u64 d; asm("fma.rn.f32x2 %0, %1, %2, %3;" : "=l"(d) : "l"(a), "l"(b), "l"(c)); return d;
}
// warp max of NON-NEGATIVE floats via single integer redux
__device__ __forceinline__ float warp_max_pos(float x) {
    int r; asm("redux.sync.max.s32 %0, %1, 0xffffffff;" : "=r"(r) : "r"(__float_as_int(x)));
    return __int_as_float(r);
}

// ---------------- forward kernel: one chain per 64-thread CTA ----------------
// Lane tid<48 owns output tag j=tid. s kept in exp domain; exact power-of-2
// renorm every 4 steps, applied LAZILY (folded into next step's exp(logit)).
__global__ __launch_bounds__(64) void crf_fwd_kernel(
    const float* __restrict__ logits,   // [B, L, T]
    const float* __restrict__ trans,    // [T, T]
    const int*   __restrict__ labels,   // [B, L]
    const int*   __restrict__ lens)     // [B]
{
    __shared__ __align__(16) float sbuf[2][NT];   // ping-pong s vectors
    __shared__ float smax[2];                     // per-warp maxes for renorm
    __shared__ float sred[2][2];                  // epilogue reductions

    const int  tid = threadIdx.x;
    const int  wrp = tid >> 5;
    const bool act = (tid < NT);
    const int  j   = act ? tid : 0;

    // exp(transitions) row for this lane's output tag, packed in k-pairs.
    // exp(-1e4) underflows to exactly 0 == semiring zero.
    u64 tr[24];
#pragma unroll
    for (int q = 0; q < 24; q++) {
        float e0 = act ? __expf(trans[j * TT + 2 * q])     : 0.0f;
        float e1 = act ? __expf(trans[j * TT + 2 * q + 1]) : 0.0f;
        tr[q] = pack2(e0, e1);
    }
    const float tstop = act ? __expf(trans[STOP_TAG * TT + j]) : 0.0f;

    const int b   = blockIdx.x;
    const int len = lens[b];
    const float* lg = logits + (size_t)b * (LL * TT);

    // ---- t = 0 closed form: s[j] = exp(trans[j,START] + logit0[j])
    float s = act ? __expf(trans[j * TT + START_TAG] + lg[j]) : 0.0f;
    if (act) sbuf[1][j] = s;          // read buffer for t=1 is (t&1)=1

    // logit prefetch ring, depth 2
    float pf[2];
    pf[1] = act ? lg[(size_t)min(1, len - 1) * TT + j] : 0.0f;
    pf[0] = act ? lg[(size_t)min(2, len - 1) * TT + j] : 0.0f;

    int   E  = 0;
    float sc = 1.0f;
    float w  = 0.0f;
    __syncthreads();

    if (len == 1) {
        w = s * tstop;
    } else {
#pragma unroll 2
        for (int t = 1; t < len; t++) {
            // emission factor early (hides MUFU + pending renorm scale)
            float em = __expf(pf[t & 1]) * sc;
            sc = 1.0f;
            // refill prefetch slot t+2
            pf[t & 1] = act ? lg[(size_t)min(t + 2, len - 1) * TT + j] : 0.0f;

            // matvec p = sum_k Texp[j,k] * s[k]; 4 packed accumulator chains
            const ulonglong2* sb = (const ulonglong2*)sbuf[t & 1];
            u64 a0 = 0ull, a1 = 0ull, a2 = 0ull, a3 = 0ull;
#pragma unroll
            for (int i = 0; i < 12; i++) {
                ulonglong2 v = sb[i];          // s[4i..4i+3] as two packed pairs
                if (i & 1) {
                    a2 = fma2(tr[2 * i],     v.x, a2);
                    a3 = fma2(tr[2 * i + 1], v.y, a3);
                } else {
                    a0 = fma2(tr[2 * i],     v.x, a0);
                    a1 = fma2(tr[2 * i + 1], v.y, a1);
                }
            }
            u64 aa = fma2(pack2(1.0f, 1.0f), a2, a0);
            u64 bb = fma2(pack2(1.0f, 1.0f), a3, a1);
            float x0, x1, y0, y1;
            unpack2(aa, x0, x1);
            unpack2(bb, y0, y1);
            float p = (x0 + x1) + (y0 + y1);

            s = act ? (p * em) : 0.0f;

            if (t == len - 1) {               // uniform across CTA
                w = s * tstop;
            } else {
                if (act) sbuf[(t + 1) & 1][j] = s;   // store immediately (critical path)
                const bool rn = ((t & 3) == 3);
                if (rn) {                      // off-path renorm prep
                    float mx = warp_max_pos(s);
                    if ((tid & 31) == 0) smax[wrp] = mx;
                }
                __syncthreads();
                if (rn) {
                    float m  = fmaxf(smax[0], smax[1]);   // > 0 always
                    int   e  = (__float_as_int(m) >> 23) - 127;
                    sc = __int_as_float((127 - e) << 23); // 2^{-e}, applied next step
                    E += e;                               // always applied before exit
                }
            }
        }
    }

    // ---- partition = log(sum_j s[j]*exp(trans[STOP,j])) + E*ln2
#pragma unroll
    for (int o = 16; o; o >>= 1) w += __shfl_xor_sync(0xffffffffu, w, o);
    if ((tid & 31) == 0) sred[0][wrp] = w;

    // ---- gold score: emission + label-path transitions (64-thread stride)
    const int* labs = labels + (size_t)b * LL;
    float gold = 0.0f;
    for (int t2 = tid; t2 < len; t2 += 64) {
        int lab  = labs[t2];
        int prev = t2 ? labs[t2 - 1] : START_TAG;
        gold += lg[(size_t)t2 * TT + lab] + trans[lab * TT + prev];
    }
#pragma unroll
    for (int o = 16; o; o >>= 1) gold += __shfl_xor_sync(0xffffffffu, gold, o);
    if ((tid & 31) == 0) sred[1][wrp] = gold;
    __syncthreads();

    if (tid == 0) {
        float wt = sred[0][0] + sred[0][1];
        float partition = logf(wt) + (float)E * 0.69314718055994530942f;
        float g = sred[1][0] + sred[1][1] + trans[STOP_TAG * TT + labs[len - 1]];
        g_nll[b] = partition - g;
    }
}

__global__ __launch_bounds__(1024) void crf_reduce_kernel(float* __restrict__ out) {
    __shared__ float sh[32];
    int tid = threadIdx.x;
    float s = g_nll[tid];
#pragma unroll
    for (int o = 16; o; o >>= 1) s += __shfl_xor_sync(0xffffffffu, s, o);
    if ((tid & 31) == 0) sh[tid >> 5] = s;
    __syncthreads();
    if (tid < 32) {
        float v = sh[tid];
#pragma unroll
        for (int o = 16; o; o >>= 1) v += __shfl_xor_sync(0xffffffffu, v, o);
        if (tid == 0) out[0] = v / (float)BB;
    }
}

extern "C" void kernel_launch(void* const* d_in, const int* in_sizes, int n_in,
                              void* d_out, int out_size) {
    const float* logits = (const float*)d_in[0];
    const float* trans  = (const float*)d_in[1];
    const int*   labels = (const int*)d_in[2];
    const int*   lens   = (const int*)d_in[3];

    crf_fwd_kernel<<<BB, 64>>>(logits, trans, labels, lens);
    crf_reduce_kernel<<<1, 1024>>>((float*)d_out);
}

// round 6
// speedup vs baseline: 2.2284x; 1.7606x over previous
#include <cuda_runtime.h>
#include <cstdint>

#define BB 1024
#define LL 512
#define TT 50
#define NT 48
#define START_TAG 48
#define STOP_TAG  49

typedef unsigned long long u64;

__device__ float g_nll[BB];
__device__ int   g_perm[BB];

__device__ __forceinline__ u64 pack2(float x, float y) {
    u64 u; asm("mov.b64 %0, {%1,%2};" : "=l"(u) : "f"(x), "f"(y)); return u;
}
__device__ __forceinline__ void unpack2(u64 u, float &x, float &y) {
    asm("mov.b64 {%0,%1}, %2;" : "=f"(x), "=f"(y) : "l"(u));
}
__device__ __forceinline__ u64 fma2(u64 a, u64 b, u64 c) {
    u64 d; asm("fma.rn.f32x2 %0, %1, %2, %3;" : "=l"(d) : "l"(a), "l"(b), "l"(c)); return d;
}
// warp max of NON-NEGATIVE floats via single integer redux
__device__ __forceinline__ float warp_max_pos(float x) {
    int r; asm("redux.sync.max.s32 %0, %1, 0xffffffff;" : "=r"(r) : "r"(__float_as_int(x)));
    return __int_as_float(r);
}

// ---------- scheduling: counting sort of chains by descending len ----------
__global__ __launch_bounds__(1024) void crf_sort_kernel(const int* __restrict__ lens) {
    __shared__ int hist[512];
    __shared__ int sc[512];
    int tid = threadIdx.x;
    if (tid < 512) hist[tid] = 0;
    __syncthreads();
    int key = 512 - lens[tid];          // len in [1,512] -> key in [0,511], descending
    atomicAdd(&hist[key], 1);
    __syncthreads();
    int orig = (tid < 512) ? hist[tid] : 0;
    int v = orig;
    for (int off = 1; off < 512; off <<= 1) {
        if (tid < 512) sc[tid] = v;
        __syncthreads();
        if (tid < 512 && tid >= off) v += sc[tid - off];
        __syncthreads();
    }
    if (tid < 512) sc[tid] = v - orig;
    __syncthreads();
    int pos = atomicAdd(&sc[key], 1);
    g_perm[pos] = tid;
}

// ---------- 48x48 matvec over packed pairs (R2 lane mapping) ----------
// Lane pair (2m,2m+1): each lane fully owns output jF=3m+(l&1); shared output
// jS=3m+2 split over k-halves (shb) and combined with one shfl.
__device__ __forceinline__ void matvec48(const u64* __restrict__ rF,
                                         const u64* __restrict__ rS,
                                         const ulonglong2* __restrict__ sb,
                                         int shb, bool odd,
                                         float& pF, float& pSh)
{
    u64 a0 = 0ull, a1 = 0ull, as0 = 0ull, as1 = 0ull;
#pragma unroll
    for (int q = 0; q < 12; q++) {
        ulonglong2 sp = sb[q];
        a0 = fma2(rF[2 * q],     sp.x, a0);
        a1 = fma2(rF[2 * q + 1], sp.y, a1);
    }
#pragma unroll
    for (int q = 0; q < 6; q++) {
        ulonglong2 sp = sb[shb + q];
        as0 = fma2(rS[2 * q],     sp.x, as0);
        as1 = fma2(rS[2 * q + 1], sp.y, as1);
    }
    const u64 ONE = pack2(1.0f, 1.0f);
    u64 af = fma2(ONE, a1, a0);
    float f0, f1; unpack2(af, f0, f1);
    pF = f0 + f1;
    u64 ash = fma2(ONE, as1, as0);
    float g0, g1; unpack2(ash, g0, g1);
    float ph = g0 + g1;
    pSh = ph + __shfl_xor_sync(0xffffffffu, ph, 1);
}

// ---------- generic chain runner: nsteps matvec+emission steps ----------
// Consumes logits at index base + dir*t for t=1..nsteps. State in buf ping-pong
// (closed form pre-stored in buf[1]). Lazy exact power-of-2 renorm every 4.
__device__ __forceinline__ void run_steps(
    int nsteps, const float* __restrict__ lg, int base, int dir,
    const u64* __restrict__ rF, const u64* __restrict__ rS,
    u64 (*buf)[24], int shb, bool odd, int jF, int jS,
    float& sF, float& sS, int& E, float& sc)
{
    if (nsteps <= 0) return;

    float pfF[2], pfS[2];
    {
        int i1 = base + dir;
        int i2 = base + dir * min(2, nsteps);
        pfF[1] = lg[(size_t)i1 * TT + jF];
        pfS[1] = odd ? lg[(size_t)i1 * TT + jS] : 0.0f;
        pfF[0] = lg[(size_t)i2 * TT + jF];
        pfS[0] = odd ? lg[(size_t)i2 * TT + jS] : 0.0f;
    }

#pragma unroll 2
    for (int t = 1; t <= nsteps; t++) {
        float emF = __expf(pfF[t & 1]) * sc;
        float emS = __expf(pfS[t & 1]) * sc;
        sc = 1.0f;
        {
            int tp = min(t + 2, nsteps);
            const float* rp = lg + (size_t)(base + dir * tp) * TT;
            pfF[t & 1] = rp[jF];
            pfS[t & 1] = odd ? rp[jS] : 0.0f;
        }
        float pF, pSh;
        matvec48(rF, rS, (const ulonglong2*)buf[t & 1], shb, odd, pF, pSh);
        sF = pF * emF;
        sS = odd ? (pSh * emS) : 0.0f;
        float* sw = (float*)buf[(t + 1) & 1];
        sw[jF] = sF;
        if (odd) sw[jS] = sS;
        if ((t & 3) == 3) {                    // lazy renorm: applied at next em
            float mx = warp_max_pos(fmaxf(sF, sS));
            int e = (__float_as_int(mx) >> 23) - 127;
            sc = __int_as_float((127 - e) << 23);
            E += e;
        }
        __syncwarp();
    }
}

// ---------- fwd/bwd split kernel: one chain per 64-thread CTA ----------
// Warp 0: forward alpha for m=(len+1)/2 steps. Warp 1: backward row-vector
// recursion for len-m steps + one em-free matvec. Meet-in-middle dot product.
__global__ __launch_bounds__(64) void crf_fwd_kernel(
    const float* __restrict__ logits,   // [B, L, T]
    const float* __restrict__ trans,    // [T, T]
    const int*   __restrict__ labels,   // [B, L]
    const int*   __restrict__ lens)     // [B]
{
    __shared__ __align__(16) u64 bufF[2][24];
    __shared__ __align__(16) u64 bufB[2][24];
    __shared__ float sfin[NT];
    __shared__ float sgold;
    __shared__ int   sEf;

    const int  tid = threadIdx.x;
    const int  l   = tid & 31;
    const int  w   = tid >> 5;
    const int  m_  = l >> 1;
    const bool odd = (l & 1);
    const int  jF  = 3 * m_ + (odd ? 1 : 0);
    const int  jS  = 3 * m_ + 2;
    const int  shb = odd ? 6 : 0;

    const int b   = g_perm[blockIdx.x];
    const int len = lens[b];
    const float* lg = logits + (size_t)b * (LL * TT);
    const int mS  = (len + 1) >> 1;

    float rFv = 0.0f, rSv = 0.0f;
    int   Eb  = 0;

    if (w == 0) {
        // -------- forward half --------
        u64 rF[24], rS[12];
#pragma unroll
        for (int kk = 0; kk < 24; kk++)
            rF[kk] = pack2(__expf(trans[jF * TT + 2 * kk]),
                           __expf(trans[jF * TT + 2 * kk + 1]));
#pragma unroll
        for (int q = 0; q < 12; q++) {
            int kk = shb * 2 + q;
            rS[q] = pack2(__expf(trans[jS * TT + 2 * kk]),
                          __expf(trans[jS * TT + 2 * kk + 1]));
        }

        // t=0 closed form: s[j] = exp(trans[j,START] + logit0[j])
        float sF = __expf(trans[jF * TT + START_TAG] + lg[jF]);
        float sS = odd ? __expf(trans[jS * TT + START_TAG] + lg[jS]) : 0.0f;
        float* sw = (float*)bufF[1];
        sw[jF] = sF;
        if (odd) sw[jS] = sS;
        __syncwarp();

        int E = 0; float sc = 1.0f;
        run_steps(mS - 1, lg, 0, +1, rF, rS, bufF, shb, odd, jF, jS, sF, sS, E, sc);
        sF *= sc; sS *= sc;                    // apply pending renorm
        sfin[jF] = sF;
        if (odd) sfin[jS] = sS;
        if (l == 0) sEf = E;

        // -------- gold score --------
        const int* labs = labels + (size_t)b * LL;
        float gold = 0.0f;
        for (int t2 = l; t2 < len; t2 += 32) {
            int lab  = labs[t2];
            int prev = t2 ? labs[t2 - 1] : START_TAG;
            gold += lg[(size_t)t2 * TT + lab] + trans[lab * TT + prev];
        }
#pragma unroll
        for (int o = 16; o; o >>= 1) gold += __shfl_xor_sync(0xffffffffu, gold, o);
        if (l == 0) sgold = gold + trans[STOP_TAG * TT + labs[len - 1]];
    } else {
        // -------- backward half (transposed coefficients T[k, jOut]) --------
        u64 rF[24], rS[12];
#pragma unroll
        for (int kk = 0; kk < 24; kk++)
            rF[kk] = pack2(__expf(trans[(2 * kk) * TT + jF]),
                           __expf(trans[(2 * kk + 1) * TT + jF]));
#pragma unroll
        for (int q = 0; q < 12; q++) {
            int kk = shb * 2 + q;
            rS[q] = pack2(__expf(trans[(2 * kk) * TT + jS]),
                          __expf(trans[(2 * kk + 1) * TT + jS]));
        }

        if (len == 1) {
            rFv = __expf(trans[STOP_TAG * TT + jF]);
            rSv = __expf(trans[STOP_TAG * TT + jS]);
        } else {
            // closed form at u=len-1: w[j] = exp(trans[STOP,j] + logit_{len-1}[j])
            float sF = __expf(trans[STOP_TAG * TT + jF] + lg[(size_t)(len - 1) * TT + jF]);
            float sS = odd ? __expf(trans[STOP_TAG * TT + jS] + lg[(size_t)(len - 1) * TT + jS]) : 0.0f;
            float* sw = (float*)bufB[1];
            sw[jF] = sF;
            if (odd) sw[jS] = sS;
            __syncwarp();

            float sc = 1.0f;
            const int nb = len - 1 - mS;       // matvec steps down to u=mS
            run_steps(nb, lg, len - 1, -1, rF, rS, bufB, shb, odd, jF, jS, sF, sS, Eb, sc);

            // extra em-free matvec: r = T^T w_m  (scale sc folded in afterwards)
            float pF, pSh;
            matvec48(rF, rS, (const ulonglong2*)bufB[(nb + 1) & 1], shb, odd, pF, pSh);
            rFv = pF * sc;
            rSv = pSh * sc;
        }
    }

    __syncthreads();   // fwd's sfin/sEf/sgold visible to bwd warp

    if (w == 1) {
        float d = rFv * sfin[jF] + (odd ? rSv * sfin[jS] : 0.0f);
#pragma unroll
        for (int o = 16; o; o >>= 1) d += __shfl_xor_sync(0xffffffffu, d, o);
        if (l == 0) {
            float partition = logf(d) + (float)(Eb + sEf) * 0.69314718055994530942f;
            g_nll[b] = partition - sgold;
        }
    }
}

__global__ __launch_bounds__(1024) void crf_reduce_kernel(float* __restrict__ out) {
    __shared__ float sh[32];
    int tid = threadIdx.x;
    float s = g_nll[tid];
#pragma unroll
    for (int o = 16; o; o >>= 1) s += __shfl_xor_sync(0xffffffffu, s, o);
    if ((tid & 31) == 0) sh[tid >> 5] = s;
    __syncthreads();
    if (tid < 32) {
        float v = sh[tid];
#pragma unroll
        for (int o = 16; o; o >>= 1) v += __shfl_xor_sync(0xffffffffu, v, o);
        if (tid == 0) out[0] = v / (float)BB;
    }
}

extern "C" void kernel_launch(void* const* d_in, const int* in_sizes, int n_in,
                              void* d_out, int out_size) {
    const float* logits = (const float*)d_in[0];
    const float* trans  = (const float*)d_in[1];
    const int*   labels = (const int*)d_in[2];
    const int*   lens   = (const int*)d_in[3];

    crf_sort_kernel<<<1, 1024>>>(lens);
    crf_fwd_kernel<<<BB, 64>>>(logits, trans, labels, lens);
    crf_reduce_kernel<<<1, 1024>>>((float*)d_out);
}